// round 9
// baseline (speedup 1.0000x reference)
#include <cuda_runtime.h>
#include <cuda_bf16.h>
#include <cstdint>

#define NE 32
#define NH 2048
#define NI 768
#define TWO_I 1536
#define NK 4
#define TKP 8192
#define PADS 12288
#define MAXTT 128
#define BM 128
#define KC 32
#define ASTR 40
#define BSTR 72

// GEMM1 dynamic smem layout (bytes)
#define G1_RA0 0
#define G1_RA1 16384
#define G1_RB0 32768
#define G1_RB1 49152
#define G1_AH  65536
#define G1_AL  75776
#define G1_BGH 86016
#define G1_BGL 90624
#define G1_BUH 95232
#define G1_BUL 99840
#define G1_SZ  104448

// GEMM2 dynamic smem layout (bytes)
#define G2_AH0 0
#define G2_AH1 10240
#define G2_AL0 20480
#define G2_AL1 30720
#define G2_RB0 40960
#define G2_RB1 49152
#define G2_BH  57344
#define G2_BL  61952
#define G2_SZ  66560

// ---------------- device scratch ---------------------------------------------
__device__ int   g_cnt[NE];
__device__ int   g_cur[NE];
__device__ int   g_tok[PADS];
__device__ float g_w[PADS];
__device__ int   g_is64;
__device__ int   g_tile_e[MAXTT];
__device__ int   g_tile_base[MAXTT];
__device__ __nv_bfloat16 g_ih[(size_t)PADS * NI];
__device__ __nv_bfloat16 g_il[(size_t)PADS * NI];

// ---------------- helpers -----------------------------------------------------
__device__ __forceinline__ uint32_t smem_u32(const void* p) {
    uint32_t a;
    asm("{ .reg .u64 t; cvta.to.shared.u64 t, %1; cvt.u32.u64 %0, t; }" : "=r"(a) : "l"(p));
    return a;
}
#define CP16(dst, src) asm volatile("cp.async.cg.shared.global [%0], [%1], 16;" :: "r"(dst), "l"(src))
#define CP_COMMIT()    asm volatile("cp.async.commit_group;" ::: "memory")
#define CP_WAIT1()     asm volatile("cp.async.wait_group 1;" ::: "memory")
#define CP_WAIT0()     asm volatile("cp.async.wait_group 0;" ::: "memory")

__device__ __forceinline__ void ldm_x4(uint32_t* r, uint32_t addr) {
    asm volatile("ldmatrix.sync.aligned.m8n8.x4.shared.b16 {%0,%1,%2,%3}, [%4];"
        : "=r"(r[0]), "=r"(r[1]), "=r"(r[2]), "=r"(r[3]) : "r"(addr));
}
__device__ __forceinline__ void ldm_x4t(uint32_t* r, uint32_t addr) {
    asm volatile("ldmatrix.sync.aligned.m8n8.x4.trans.shared.b16 {%0,%1,%2,%3}, [%4];"
        : "=r"(r[0]), "=r"(r[1]), "=r"(r[2]), "=r"(r[3]) : "r"(addr));
}
__device__ __forceinline__ void mma_bf16(float* d, const uint32_t* a, const uint32_t* b) {
    asm volatile("mma.sync.aligned.m16n8k16.row.col.f32.bf16.bf16.f32 "
        "{%0,%1,%2,%3}, {%4,%5,%6,%7}, {%8,%9}, {%0,%1,%2,%3};"
        : "+f"(d[0]), "+f"(d[1]), "+f"(d[2]), "+f"(d[3])
        : "r"(a[0]), "r"(a[1]), "r"(a[2]), "r"(a[3]), "r"(b[0]), "r"(b[1]));
}
__device__ __forceinline__ void split2(float f0, float f1, uint32_t& h, uint32_t& l) {
    __nv_bfloat162 hb = __floats2bfloat162_rn(f0, f1);
    float2 hf = __bfloat1622float2(hb);
    __nv_bfloat162 lb = __floats2bfloat162_rn(f0 - hf.x, f1 - hf.y);
    h = *reinterpret_cast<uint32_t*>(&hb);
    l = *reinterpret_cast<uint32_t*>(&lb);
}
__device__ __forceinline__ float silu_f(float v) { return v / (1.0f + expf(-v)); }

__device__ __forceinline__ int fetch_idx(const int* __restrict__ idx, int i, int is64) {
    return is64 ? idx[2 * i] : idx[i];
}
__device__ __forceinline__ int keep_pair(const int* __restrict__ idx, int t, int k,
                                         int e, int is64) {
    for (int k2 = k + 1; k2 < NK; k2++)
        if (fetch_idx(idx, t * NK + k2, is64) == e) return 0;
    return 1;
}

// ---------------- routing: exactly 3 kernels (gemm1 = 4th launch for ncu) -----
__global__ void k_r0(const int* __restrict__ idx) {
    int i = blockIdx.x * blockDim.x + threadIdx.x;
    if (i < PADS) { g_tok[i] = 0; g_w[i] = 0.f; }
    if (i < NE) g_cnt[i] = 0;
    if (i == 0) {
        int ok = 1;
        for (int j = 0; j < 64; j++) if (idx[2 * j + 1] != 0) { ok = 0; break; }
        g_is64 = ok;
    }
}
__global__ void k_r1(const int* __restrict__ idx) {
    int i = blockIdx.x * blockDim.x + threadIdx.x;
    if (i < TKP) {
        int is64 = g_is64;
        int t = i / NK, k = i % NK;
        int e = fetch_idx(idx, i, is64);
        if (keep_pair(idx, t, k, e, is64)) atomicAdd(&g_cnt[e], 1);
    }
}
__global__ void k_r2(const int* __restrict__ idx, const float* __restrict__ wgt) {
    int tid = threadIdx.x;
    if (tid == 0) {
        int pb = 0, tl = 0;
        for (int e = 0; e < NE; e++) {
            g_cur[e] = pb;
            int nt = (g_cnt[e] + BM - 1) / BM;
            for (int j = 0; j < nt; j++) { g_tile_e[tl] = e; g_tile_base[tl] = pb + j * BM; tl++; }
            pb += nt * BM;
        }
        for (int t2 = tl; t2 < MAXTT; t2++) g_tile_e[t2] = -1;
    }
    __syncthreads();
    int is64 = g_is64;
    for (int i = tid; i < TKP; i += blockDim.x) {
        int t = i / NK, k = i % NK;
        int e = fetch_idx(idx, i, is64);
        if (keep_pair(idx, t, k, e, is64)) {
            int pos = atomicAdd(&g_cur[e], 1);
            g_tok[pos] = t; g_w[pos] = wgt[i];
        }
    }
}

// ---------------- GEMM1 -------------------------------------------------------
__global__ __launch_bounds__(256, 2)
void k_gemm1(const float* __restrict__ x, const float* __restrict__ W1) {
    int tile = blockIdx.y;
    int e = g_tile_e[tile];
    if (e < 0) return;
    int base = g_tile_base[tile];
    int j0 = blockIdx.x * 64;
    extern __shared__ char smem[];
    uint32_t sb = smem_u32(smem);

    int tid = threadIdx.x, lane = tid & 31, wid = tid >> 5;
    int wm = wid & 3, wn = wid >> 2;
    const float* W = W1 + (size_t)e * NH * TWO_I;

    int arow = tid >> 1, acb = (tid & 1) * 16;
    const float* axp = x + (size_t)g_tok[base + arow] * NH + acb;
    int brow = tid >> 3, bc16 = (tid & 7) * 16;
    int gcol = (bc16 < 64) ? (j0 + bc16) : (NI + j0 + bc16 - 64);
    const float* bwp = W + (size_t)brow * TWO_I + gcol;
    uint32_t dA = (uint32_t)((arow * 32 + acb) * 4);
    uint32_t dB = (uint32_t)((brow * 128 + bc16) * 4);

    uint32_t sAh = sb + G1_AH, sAl = sb + G1_AL;
    uint32_t sBgh = sb + G1_BGH, sBgl = sb + G1_BGL;
    uint32_t sBuh = sb + G1_BUH, sBul = sb + G1_BUL;

    uint32_t aoff[2], boff[2];
#pragma unroll
    for (int mf = 0; mf < 2; mf++)
        aoff[mf] = (uint32_t)((wm * 32 + mf * 16 + (lane & 15)) * (ASTR * 2) + (lane >> 4) * 16);
#pragma unroll
    for (int nb = 0; nb < 2; nb++)
        boff[nb] = (uint32_t)((lane & 15) * (BSTR * 2) + (wn * 32 + nb * 16 + (lane >> 4) * 8) * 2);

    float accg[2][4][4] = {}, accu[2][4][4] = {};
    const int NC = NH / KC;

#pragma unroll
    for (int p = 0; p < 2; p++) {
        uint32_t rA = sb + (p ? G1_RA1 : G1_RA0) + dA;
        uint32_t rB = sb + (p ? G1_RB1 : G1_RB0) + dB;
        const float* sa = axp + p * KC;
        const float* sw = bwp + (size_t)(p * KC) * TWO_I;
#pragma unroll
        for (int j = 0; j < 4; j++) CP16(rA + j * 16, sa + j * 4);
#pragma unroll
        for (int j = 0; j < 4; j++) CP16(rB + j * 16, sw + j * 4);
        CP_COMMIT();
    }

    for (int c = 0; c < NC; c++) {
        int st = c & 1;
        if (c == NC - 1) CP_WAIT0(); else CP_WAIT1();
        __syncthreads();
        // ---- convert raw -> bf16 hi/lo smem ----
        {
            const float* rA = (const float*)(smem + (st ? G1_RA1 : G1_RA0));
            const float* rB = (const float*)(smem + (st ? G1_RB1 : G1_RB0));
            __nv_bfloat16* Ah = (__nv_bfloat16*)(smem + G1_AH);
            __nv_bfloat16* Al = (__nv_bfloat16*)(smem + G1_AL);
            int oA = arow * ASTR + acb;
            const float* pa = rA + arow * 32 + acb;
#pragma unroll
            for (int j = 0; j < 8; j++) {
                uint32_t h, l;
                split2(pa[2 * j], pa[2 * j + 1], h, l);
                *(uint32_t*)&Ah[oA + 2 * j] = h;
                *(uint32_t*)&Al[oA + 2 * j] = l;
            }
            const float* pb = rB + brow * 128 + bc16;
            __nv_bfloat16* Bh = (__nv_bfloat16*)(smem + ((bc16 < 64) ? G1_BGH : G1_BUH));
            __nv_bfloat16* Bl = (__nv_bfloat16*)(smem + ((bc16 < 64) ? G1_BGL : G1_BUL));
            int oB = brow * BSTR + ((bc16 < 64) ? bc16 : bc16 - 64);
#pragma unroll
            for (int j = 0; j < 8; j++) {
                uint32_t h, l;
                split2(pb[2 * j], pb[2 * j + 1], h, l);
                *(uint32_t*)&Bh[oB + 2 * j] = h;
                *(uint32_t*)&Bl[oB + 2 * j] = l;
            }
        }
        __syncthreads();
        // ---- issue cp.async for chunk c+2 into this (now-consumed) raw stage ----
        if (c + 2 < NC) {
            int k0 = (c + 2) * KC;
            uint32_t rA = sb + (st ? G1_RA1 : G1_RA0) + dA;
            uint32_t rB = sb + (st ? G1_RB1 : G1_RB0) + dB;
            const float* sa = axp + k0;
            const float* sw = bwp + (size_t)k0 * TWO_I;
#pragma unroll
            for (int j = 0; j < 4; j++) CP16(rA + j * 16, sa + j * 4);
#pragma unroll
            for (int j = 0; j < 4; j++) CP16(rB + j * 16, sw + j * 4);
        }
        CP_COMMIT();
        // ---- MMA (reads conv bufs; cp writes raw bufs — disjoint) ----
#pragma unroll
        for (int s = 0; s < 2; s++) {
            uint32_t ah[2][4], al[2][4], bg[2][4], bu[2][4];
            uint32_t as_ = (uint32_t)(s * 32), bs_ = (uint32_t)(s * 16 * BSTR * 2);
            ldm_x4(ah[0], sAh + aoff[0] + as_);
            ldm_x4(ah[1], sAh + aoff[1] + as_);
            ldm_x4(al[0], sAl + aoff[0] + as_);
            ldm_x4(al[1], sAl + aoff[1] + as_);
            ldm_x4t(bg[0], sBgh + boff[0] + bs_);
            ldm_x4t(bg[1], sBgh + boff[1] + bs_);
            ldm_x4t(bu[0], sBuh + boff[0] + bs_);
            ldm_x4t(bu[1], sBuh + boff[1] + bs_);
#pragma unroll
            for (int mf = 0; mf < 2; mf++)
#pragma unroll
                for (int nb = 0; nb < 2; nb++)
#pragma unroll
                    for (int f = 0; f < 2; f++) {
                        mma_bf16(accg[mf][nb * 2 + f], ah[mf], &bg[nb][f * 2]);
                        mma_bf16(accu[mf][nb * 2 + f], ah[mf], &bu[nb][f * 2]);
                        mma_bf16(accg[mf][nb * 2 + f], al[mf], &bg[nb][f * 2]);
                        mma_bf16(accu[mf][nb * 2 + f], al[mf], &bu[nb][f * 2]);
                    }
            ldm_x4t(bg[0], sBgl + boff[0] + bs_);
            ldm_x4t(bg[1], sBgl + boff[1] + bs_);
            ldm_x4t(bu[0], sBul + boff[0] + bs_);
            ldm_x4t(bu[1], sBul + boff[1] + bs_);
#pragma unroll
            for (int mf = 0; mf < 2; mf++)
#pragma unroll
                for (int nb = 0; nb < 2; nb++)
#pragma unroll
                    for (int f = 0; f < 2; f++) {
                        mma_bf16(accg[mf][nb * 2 + f], ah[mf], &bg[nb][f * 2]);
                        mma_bf16(accu[mf][nb * 2 + f], ah[mf], &bu[nb][f * 2]);
                    }
        }
    }

    // ---- epilogue ----
#pragma unroll
    for (int mf = 0; mf < 2; mf++) {
        int rA = base + wm * 32 + mf * 16 + (lane >> 2);
        float wa = g_w[rA], wb = g_w[rA + 8];
#pragma unroll
        for (int nf = 0; nf < 4; nf++) {
            int col = j0 + wn * 32 + nf * 8 + (lane & 3) * 2;
            float o0 = silu_f(accg[mf][nf][0]) * accu[mf][nf][0] * wa;
            float o1 = silu_f(accg[mf][nf][1]) * accu[mf][nf][1] * wa;
            float o2 = silu_f(accg[mf][nf][2]) * accu[mf][nf][2] * wb;
            float o3 = silu_f(accg[mf][nf][3]) * accu[mf][nf][3] * wb;
            uint32_t h, l;
            split2(o0, o1, h, l);
            *(uint32_t*)&g_ih[(size_t)rA * NI + col] = h;
            *(uint32_t*)&g_il[(size_t)rA * NI + col] = l;
            split2(o2, o3, h, l);
            *(uint32_t*)&g_ih[(size_t)(rA + 8) * NI + col] = h;
            *(uint32_t*)&g_il[(size_t)(rA + 8) * NI + col] = l;
        }
    }
}

// ---------------- GEMM2 -------------------------------------------------------
__global__ __launch_bounds__(256, 2)
void k_gemm2(const float* __restrict__ W2, float* __restrict__ out) {
    int tile = blockIdx.y;
    int e = g_tile_e[tile];
    if (e < 0) return;
    int base = g_tile_base[tile];
    int n0 = blockIdx.x * 64;
    extern __shared__ char smem[];
    uint32_t sb = smem_u32(smem);

    int tid = threadIdx.x, lane = tid & 31, wid = tid >> 5;
    int wm = wid & 3, wn = wid >> 2;
    const float* W = W2 + (size_t)e * NI * NH;

    int arow = tid >> 1, ahalf = tid & 1;
    const __nv_bfloat16* aih = g_ih + (size_t)(base + arow) * NI + ahalf * 16;
    const __nv_bfloat16* ail = g_il + (size_t)(base + arow) * NI + ahalf * 16;
    uint32_t dA = (uint32_t)(arow * (ASTR * 2) + ahalf * 32);
    int brow = tid >> 3, bc8 = (tid & 7) * 8;
    const float* bwp = W + (size_t)brow * NH + n0 + bc8;
    uint32_t dB = (uint32_t)((brow * 64 + bc8) * 4);

    uint32_t sBh = sb + G2_BH, sBl = sb + G2_BL;

    uint32_t aoff[2], boff[2];
#pragma unroll
    for (int mf = 0; mf < 2; mf++)
        aoff[mf] = (uint32_t)((wm * 32 + mf * 16 + (lane & 15)) * (ASTR * 2) + (lane >> 4) * 16);
#pragma unroll
    for (int nb = 0; nb < 2; nb++)
        boff[nb] = (uint32_t)((lane & 15) * (BSTR * 2) + (wn * 32 + nb * 16 + (lane >> 4) * 8) * 2);

    float acc[2][4][4] = {};
    const int NC = NI / KC;

#pragma unroll
    for (int p = 0; p < 2; p++) {
        uint32_t rAh = sb + (p ? G2_AH1 : G2_AH0) + dA;
        uint32_t rAl = sb + (p ? G2_AL1 : G2_AL0) + dA;
        uint32_t rB  = sb + (p ? G2_RB1 : G2_RB0) + dB;
        const __nv_bfloat16* sh = aih + p * KC;
        const __nv_bfloat16* sl = ail + p * KC;
        const float* sw = bwp + (size_t)(p * KC) * NH;
        CP16(rAh, sh);      CP16(rAh + 16, sh + 8);
        CP16(rAl, sl);      CP16(rAl + 16, sl + 8);
        CP16(rB, sw);       CP16(rB + 16, sw + 4);
        CP_COMMIT();
    }

    for (int c = 0; c < NC; c++) {
        int st = c & 1;
        if (c == NC - 1) CP_WAIT0(); else CP_WAIT1();
        __syncthreads();
        // ---- convert raw B -> bf16 hi/lo ----
        {
            const float* rB = (const float*)(smem + (st ? G2_RB1 : G2_RB0));
            __nv_bfloat16* Bh = (__nv_bfloat16*)(smem + G2_BH);
            __nv_bfloat16* Bl = (__nv_bfloat16*)(smem + G2_BL);
            const float* pb = rB + brow * 64 + bc8;
            int oB = brow * BSTR + bc8;
#pragma unroll
            for (int j = 0; j < 4; j++) {
                uint32_t h, l;
                split2(pb[2 * j], pb[2 * j + 1], h, l);
                *(uint32_t*)&Bh[oB + 2 * j] = h;
                *(uint32_t*)&Bl[oB + 2 * j] = l;
            }
        }
        __syncthreads();
        uint32_t sAh = sb + (st ? G2_AH1 : G2_AH0);
        uint32_t sAl = sb + (st ? G2_AL1 : G2_AL0);
        // ---- MMA: reads A stage st + B conv bufs (NO cp.async in flight to these) ----
#pragma unroll
        for (int s = 0; s < 2; s++) {
            uint32_t ah[2][4], al[2][4], bb[2][4];
            uint32_t as_ = (uint32_t)(s * 32), bs_ = (uint32_t)(s * 16 * BSTR * 2);
            ldm_x4(ah[0], sAh + aoff[0] + as_);
            ldm_x4(ah[1], sAh + aoff[1] + as_);
            ldm_x4(al[0], sAl + aoff[0] + as_);
            ldm_x4(al[1], sAl + aoff[1] + as_);
            ldm_x4t(bb[0], sBh + boff[0] + bs_);
            ldm_x4t(bb[1], sBh + boff[1] + bs_);
#pragma unroll
            for (int mf = 0; mf < 2; mf++)
#pragma unroll
                for (int nb = 0; nb < 2; nb++)
#pragma unroll
                    for (int f = 0; f < 2; f++) {
                        mma_bf16(acc[mf][nb * 2 + f], ah[mf], &bb[nb][f * 2]);
                        mma_bf16(acc[mf][nb * 2 + f], al[mf], &bb[nb][f * 2]);
                    }
            ldm_x4t(bb[0], sBl + boff[0] + bs_);
            ldm_x4t(bb[1], sBl + boff[1] + bs_);
#pragma unroll
            for (int mf = 0; mf < 2; mf++)
#pragma unroll
                for (int nb = 0; nb < 2; nb++)
#pragma unroll
                    for (int f = 0; f < 2; f++)
                        mma_bf16(acc[mf][nb * 2 + f], ah[mf], &bb[nb][f * 2]);
        }
        __syncthreads();   // ALL threads done reading stage st before refilling it
        // ---- FIX R8: issue refill of stage st only after MMA consumed it ----
        if (c + 2 < NC) {
            int k0 = (c + 2) * KC;
            uint32_t rAh = sb + (st ? G2_AH1 : G2_AH0) + dA;
            uint32_t rAl = sb + (st ? G2_AL1 : G2_AL0) + dA;
            uint32_t rB  = sb + (st ? G2_RB1 : G2_RB0) + dB;
            const __nv_bfloat16* sh = aih + k0;
            const __nv_bfloat16* sl = ail + k0;
            const float* sw = bwp + (size_t)k0 * NH;
            CP16(rAh, sh);      CP16(rAh + 16, sh + 8);
            CP16(rAl, sl);      CP16(rAl + 16, sl + 8);
            CP16(rB, sw);       CP16(rB + 16, sw + 4);
        }
        CP_COMMIT();
    }

#pragma unroll
    for (int mf = 0; mf < 2; mf++) {
        int rA = base + wm * 32 + mf * 16 + (lane >> 2);
        int tA = g_tok[rA], tB = g_tok[rA + 8];
#pragma unroll
        for (int nf = 0; nf < 4; nf++) {
            int col = n0 + wn * 32 + nf * 8 + (lane & 3) * 2;
            atomicAdd(&out[(size_t)tA * NH + col],     acc[mf][nf][0]);
            atomicAdd(&out[(size_t)tA * NH + col + 1], acc[mf][nf][1]);
            atomicAdd(&out[(size_t)tB * NH + col],     acc[mf][nf][2]);
            atomicAdd(&out[(size_t)tB * NH + col + 1], acc[mf][nf][3]);
        }
    }
}

// ---------------- launcher ----------------------------------------------------
extern "C" void kernel_launch(void* const* d_in, const int* in_sizes, int n_in,
                              void* d_out, int out_size) {
    const float* x   = (const float*)d_in[0];
    const int*   idx = (const int*)d_in[1];
    const float* w   = (const float*)d_in[2];
    const float* W1  = (const float*)d_in[3];
    const float* W2  = (const float*)d_in[4];
    float* out = (float*)d_out;

    static int attr_done = 0;
    if (!attr_done) {
        cudaFuncSetAttribute(k_gemm1, cudaFuncAttributeMaxDynamicSharedMemorySize, G1_SZ);
        cudaFuncSetAttribute(k_gemm2, cudaFuncAttributeMaxDynamicSharedMemorySize, G2_SZ);
        attr_done = 1;
    }

    cudaMemsetAsync(out, 0, (size_t)out_size * sizeof(float));

    k_r0<<<(PADS + 255) / 256, 256>>>(idx);
    k_r1<<<TKP / 256, 256>>>(idx);
    k_r2<<<1, 256>>>(idx, w);

    dim3 g1(NI / 64, MAXTT);
    k_gemm1<<<g1, 256, G1_SZ>>>(x, W1);

    dim3 g2(NH / 64, MAXTT);
    k_gemm2<<<g2, 256, G2_SZ>>>(W2, out);
}

// round 10
// speedup vs baseline: 1.3873x; 1.3873x over previous
#include <cuda_runtime.h>
#include <cuda_bf16.h>
#include <cstdint>

#define NE 32
#define NH 2048
#define NI 768
#define TWO_I 1536
#define NK 4
#define TKP 8192
#define PADS 12288
#define MAXTT 128
#define BM 128
#define KC 32
#define ASTR 40
#define BSTR 72

// ---------------- device scratch ---------------------------------------------
__device__ int   g_cnt[NE];
__device__ int   g_cur[NE];
__device__ int   g_tok[PADS];
__device__ float g_w[PADS];
__device__ int   g_is64;
__device__ int   g_tile_e[MAXTT];
__device__ int   g_tile_base[MAXTT];
__device__ __nv_bfloat16 g_ih[(size_t)PADS * NI];
__device__ __nv_bfloat16 g_il[(size_t)PADS * NI];

// ---------------- helpers -----------------------------------------------------
__device__ __forceinline__ uint32_t smem_u32(const void* p) {
    uint32_t a;
    asm("{ .reg .u64 t; cvta.to.shared.u64 t, %1; cvt.u32.u64 %0, t; }" : "=r"(a) : "l"(p));
    return a;
}
__device__ __forceinline__ void ldm_x4(uint32_t* r, uint32_t addr) {
    asm volatile("ldmatrix.sync.aligned.m8n8.x4.shared.b16 {%0,%1,%2,%3}, [%4];"
        : "=r"(r[0]), "=r"(r[1]), "=r"(r[2]), "=r"(r[3]) : "r"(addr));
}
__device__ __forceinline__ void ldm_x4t(uint32_t* r, uint32_t addr) {
    asm volatile("ldmatrix.sync.aligned.m8n8.x4.trans.shared.b16 {%0,%1,%2,%3}, [%4];"
        : "=r"(r[0]), "=r"(r[1]), "=r"(r[2]), "=r"(r[3]) : "r"(addr));
}
__device__ __forceinline__ void mma_bf16(float* d, const uint32_t* a, const uint32_t* b) {
    asm volatile("mma.sync.aligned.m16n8k16.row.col.f32.bf16.bf16.f32 "
        "{%0,%1,%2,%3}, {%4,%5,%6,%7}, {%8,%9}, {%0,%1,%2,%3};"
        : "+f"(d[0]), "+f"(d[1]), "+f"(d[2]), "+f"(d[3])
        : "r"(a[0]), "r"(a[1]), "r"(a[2]), "r"(a[3]), "r"(b[0]), "r"(b[1]));
}
__device__ __forceinline__ void split2(float f0, float f1, uint32_t& h, uint32_t& l) {
    __nv_bfloat162 hb = __floats2bfloat162_rn(f0, f1);
    float2 hf = __bfloat1622float2(hb);
    __nv_bfloat162 lb = __floats2bfloat162_rn(f0 - hf.x, f1 - hf.y);
    h = *reinterpret_cast<uint32_t*>(&hb);
    l = *reinterpret_cast<uint32_t*>(&lb);
}
__device__ __forceinline__ float silu_f(float v) { return v / (1.0f + __expf(-v)); }

__device__ __forceinline__ int fetch_idx(const int* __restrict__ idx, int i, int is64) {
    return is64 ? idx[2 * i] : idx[i];
}
__device__ __forceinline__ int keep_pair(const int* __restrict__ idx, int t, int k,
                                         int e, int is64) {
    for (int k2 = k + 1; k2 < NK; k2++)
        if (fetch_idx(idx, t * NK + k2, is64) == e) return 0;
    return 1;
}

// ---------------- routing: exactly 3 kernels (gemm1 = 4th launch for ncu) -----
__global__ void k_r0(const int* __restrict__ idx) {
    int i = blockIdx.x * blockDim.x + threadIdx.x;
    if (i < PADS) { g_tok[i] = 0; g_w[i] = 0.f; }
    if (i < NE) g_cnt[i] = 0;
    if (i == 0) {
        int ok = 1;
        for (int j = 0; j < 64; j++) if (idx[2 * j + 1] != 0) { ok = 0; break; }
        g_is64 = ok;
    }
}
__global__ void k_r1(const int* __restrict__ idx) {
    int i = blockIdx.x * blockDim.x + threadIdx.x;
    if (i < TKP) {
        int is64 = g_is64;
        int t = i / NK, k = i % NK;
        int e = fetch_idx(idx, i, is64);
        if (keep_pair(idx, t, k, e, is64)) atomicAdd(&g_cnt[e], 1);
    }
}
__global__ void k_r2(const int* __restrict__ idx, const float* __restrict__ wgt) {
    int tid = threadIdx.x;
    if (tid == 0) {
        int pb = 0, tl = 0;
        for (int e = 0; e < NE; e++) {
            g_cur[e] = pb;
            int nt = (g_cnt[e] + BM - 1) / BM;
            for (int j = 0; j < nt; j++) { g_tile_e[tl] = e; g_tile_base[tl] = pb + j * BM; tl++; }
            pb += nt * BM;
        }
        for (int t2 = tl; t2 < MAXTT; t2++) g_tile_e[t2] = -1;
    }
    __syncthreads();
    int is64 = g_is64;
    for (int i = tid; i < TKP; i += blockDim.x) {
        int t = i / NK, k = i % NK;
        int e = fetch_idx(idx, i, is64);
        if (keep_pair(idx, t, k, e, is64)) {
            int pos = atomicAdd(&g_cur[e], 1);
            g_tok[pos] = t; g_w[pos] = wgt[i];
        }
    }
}

// ---------------- GEMM1: inter = silu(x@Wg)*(x@Wu)*w -------------------------
__global__ __launch_bounds__(256, 2)
void k_gemm1(const float* __restrict__ x, const float* __restrict__ W1) {
    int tile = blockIdx.y;
    int e = g_tile_e[tile];
    if (e < 0) return;
    int base = g_tile_base[tile];
    int j0 = blockIdx.x * 64;

    __shared__ __align__(16) __nv_bfloat16 Ah[BM * ASTR], Al[BM * ASTR];
    __shared__ __align__(16) __nv_bfloat16 Bgh[KC * BSTR], Bgl[KC * BSTR];
    __shared__ __align__(16) __nv_bfloat16 Buh[KC * BSTR], Bul[KC * BSTR];

    int tid = threadIdx.x, lane = tid & 31, wid = tid >> 5;
    int wm = wid & 3, wn = wid >> 2;

    const float* W = W1 + (size_t)e * NH * TWO_I;

    int arow = tid >> 1, akp = (tid & 1) * 16;
    const float* xrow = x + (size_t)g_tok[base + arow] * NH + akp;
    int bkr = tid >> 3, bc = (tid & 7) * 8;
    const float* wbase = W + (size_t)bkr * TWO_I + j0 + bc;
    int oA = arow * ASTR + akp;
    int oB = bkr * BSTR + bc;

    uint32_t sAh = smem_u32(Ah), sAl = smem_u32(Al);
    uint32_t sBgh = smem_u32(Bgh), sBgl = smem_u32(Bgl);
    uint32_t sBuh = smem_u32(Buh), sBul = smem_u32(Bul);

    uint32_t aoff[2], boff[2];
#pragma unroll
    for (int mf = 0; mf < 2; mf++)
        aoff[mf] = (uint32_t)((wm * 32 + mf * 16 + (lane & 15)) * (ASTR * 2) + (lane >> 4) * 16);
#pragma unroll
    for (int nb = 0; nb < 2; nb++)
        boff[nb] = (uint32_t)((lane & 15) * (BSTR * 2) + (wn * 32 + nb * 16 + (lane >> 4) * 8) * 2);

    float accg[2][4][4] = {}, accu[2][4][4] = {};
    const int NC = NH / KC;

    // ---- prologue: direct load + split + store chunk 0 ----
    {
        const float4* px = (const float4*)xrow;
        float4 a0 = px[0], a1 = px[1], a2 = px[2], a3 = px[3];
        float4 gg0 = *(const float4*)wbase,        gg1 = *(const float4*)(wbase + 4);
        float4 uu0 = *(const float4*)(wbase + NI), uu1 = *(const float4*)(wbase + NI + 4);
        uint32_t h, l;
        split2(a0.x, a0.y, h, l); *(uint32_t*)&Ah[oA + 0]  = h; *(uint32_t*)&Al[oA + 0]  = l;
        split2(a0.z, a0.w, h, l); *(uint32_t*)&Ah[oA + 2]  = h; *(uint32_t*)&Al[oA + 2]  = l;
        split2(a1.x, a1.y, h, l); *(uint32_t*)&Ah[oA + 4]  = h; *(uint32_t*)&Al[oA + 4]  = l;
        split2(a1.z, a1.w, h, l); *(uint32_t*)&Ah[oA + 6]  = h; *(uint32_t*)&Al[oA + 6]  = l;
        split2(a2.x, a2.y, h, l); *(uint32_t*)&Ah[oA + 8]  = h; *(uint32_t*)&Al[oA + 8]  = l;
        split2(a2.z, a2.w, h, l); *(uint32_t*)&Ah[oA + 10] = h; *(uint32_t*)&Al[oA + 10] = l;
        split2(a3.x, a3.y, h, l); *(uint32_t*)&Ah[oA + 12] = h; *(uint32_t*)&Al[oA + 12] = l;
        split2(a3.z, a3.w, h, l); *(uint32_t*)&Ah[oA + 14] = h; *(uint32_t*)&Al[oA + 14] = l;
        split2(gg0.x, gg0.y, h, l); *(uint32_t*)&Bgh[oB + 0] = h; *(uint32_t*)&Bgl[oB + 0] = l;
        split2(gg0.z, gg0.w, h, l); *(uint32_t*)&Bgh[oB + 2] = h; *(uint32_t*)&Bgl[oB + 2] = l;
        split2(gg1.x, gg1.y, h, l); *(uint32_t*)&Bgh[oB + 4] = h; *(uint32_t*)&Bgl[oB + 4] = l;
        split2(gg1.z, gg1.w, h, l); *(uint32_t*)&Bgh[oB + 6] = h; *(uint32_t*)&Bgl[oB + 6] = l;
        split2(uu0.x, uu0.y, h, l); *(uint32_t*)&Buh[oB + 0] = h; *(uint32_t*)&Bul[oB + 0] = l;
        split2(uu0.z, uu0.w, h, l); *(uint32_t*)&Buh[oB + 2] = h; *(uint32_t*)&Bul[oB + 2] = l;
        split2(uu1.x, uu1.y, h, l); *(uint32_t*)&Buh[oB + 4] = h; *(uint32_t*)&Bul[oB + 4] = l;
        split2(uu1.z, uu1.w, h, l); *(uint32_t*)&Buh[oB + 6] = h; *(uint32_t*)&Bul[oB + 6] = l;
    }
    __syncthreads();

    for (int c = 0; c < NC; c++) {
        bool more = (c + 1 < NC);
        // ---- prefetch next B (DRAM weights) into registers over the MMA ----
        float4 gg0, gg1, uu0, uu1;
        if (more) {
            const float* pg = wbase + (size_t)((c + 1) * KC) * TWO_I;
            gg0 = *(const float4*)pg;        gg1 = *(const float4*)(pg + 4);
            uu0 = *(const float4*)(pg + NI); uu1 = *(const float4*)(pg + NI + 4);
        }
        // ---- MMA on chunk c ----
#pragma unroll
        for (int s = 0; s < 2; s++) {
            uint32_t ah[2][4], al[2][4], bg[2][4], bu[2][4];
            uint32_t as_ = (uint32_t)(s * 32), bs_ = (uint32_t)(s * 16 * BSTR * 2);
            ldm_x4(ah[0], sAh + aoff[0] + as_);
            ldm_x4(ah[1], sAh + aoff[1] + as_);
            ldm_x4(al[0], sAl + aoff[0] + as_);
            ldm_x4(al[1], sAl + aoff[1] + as_);
            ldm_x4t(bg[0], sBgh + boff[0] + bs_);
            ldm_x4t(bg[1], sBgh + boff[1] + bs_);
            ldm_x4t(bu[0], sBuh + boff[0] + bs_);
            ldm_x4t(bu[1], sBuh + boff[1] + bs_);
#pragma unroll
            for (int mf = 0; mf < 2; mf++)
#pragma unroll
                for (int nb = 0; nb < 2; nb++)
#pragma unroll
                    for (int f = 0; f < 2; f++) {
                        mma_bf16(accg[mf][nb * 2 + f], ah[mf], &bg[nb][f * 2]);
                        mma_bf16(accu[mf][nb * 2 + f], ah[mf], &bu[nb][f * 2]);
                        mma_bf16(accg[mf][nb * 2 + f], al[mf], &bg[nb][f * 2]);
                        mma_bf16(accu[mf][nb * 2 + f], al[mf], &bu[nb][f * 2]);
                    }
            ldm_x4t(bg[0], sBgl + boff[0] + bs_);
            ldm_x4t(bg[1], sBgl + boff[1] + bs_);
            ldm_x4t(bu[0], sBul + boff[0] + bs_);
            ldm_x4t(bu[1], sBul + boff[1] + bs_);
#pragma unroll
            for (int mf = 0; mf < 2; mf++)
#pragma unroll
                for (int nb = 0; nb < 2; nb++)
#pragma unroll
                    for (int f = 0; f < 2; f++) {
                        mma_bf16(accg[mf][nb * 2 + f], ah[mf], &bg[nb][f * 2]);
                        mma_bf16(accu[mf][nb * 2 + f], ah[mf], &bu[nb][f * 2]);
                    }
        }
        __syncthreads();
        // ---- store chunk c+1: A loaded directly (L2-resident x), B from regs --
        if (more) {
            const float4* px = (const float4*)(xrow + (c + 1) * KC);
            float4 a0 = px[0], a1 = px[1], a2 = px[2], a3 = px[3];
            uint32_t h, l;
            split2(a0.x, a0.y, h, l); *(uint32_t*)&Ah[oA + 0]  = h; *(uint32_t*)&Al[oA + 0]  = l;
            split2(a0.z, a0.w, h, l); *(uint32_t*)&Ah[oA + 2]  = h; *(uint32_t*)&Al[oA + 2]  = l;
            split2(a1.x, a1.y, h, l); *(uint32_t*)&Ah[oA + 4]  = h; *(uint32_t*)&Al[oA + 4]  = l;
            split2(a1.z, a1.w, h, l); *(uint32_t*)&Ah[oA + 6]  = h; *(uint32_t*)&Al[oA + 6]  = l;
            split2(a2.x, a2.y, h, l); *(uint32_t*)&Ah[oA + 8]  = h; *(uint32_t*)&Al[oA + 8]  = l;
            split2(a2.z, a2.w, h, l); *(uint32_t*)&Ah[oA + 10] = h; *(uint32_t*)&Al[oA + 10] = l;
            split2(a3.x, a3.y, h, l); *(uint32_t*)&Ah[oA + 12] = h; *(uint32_t*)&Al[oA + 12] = l;
            split2(a3.z, a3.w, h, l); *(uint32_t*)&Ah[oA + 14] = h; *(uint32_t*)&Al[oA + 14] = l;
            split2(gg0.x, gg0.y, h, l); *(uint32_t*)&Bgh[oB + 0] = h; *(uint32_t*)&Bgl[oB + 0] = l;
            split2(gg0.z, gg0.w, h, l); *(uint32_t*)&Bgh[oB + 2] = h; *(uint32_t*)&Bgl[oB + 2] = l;
            split2(gg1.x, gg1.y, h, l); *(uint32_t*)&Bgh[oB + 4] = h; *(uint32_t*)&Bgl[oB + 4] = l;
            split2(gg1.z, gg1.w, h, l); *(uint32_t*)&Bgh[oB + 6] = h; *(uint32_t*)&Bgl[oB + 6] = l;
            split2(uu0.x, uu0.y, h, l); *(uint32_t*)&Buh[oB + 0] = h; *(uint32_t*)&Bul[oB + 0] = l;
            split2(uu0.z, uu0.w, h, l); *(uint32_t*)&Buh[oB + 2] = h; *(uint32_t*)&Bul[oB + 2] = l;
            split2(uu1.x, uu1.y, h, l); *(uint32_t*)&Buh[oB + 4] = h; *(uint32_t*)&Bul[oB + 4] = l;
            split2(uu1.z, uu1.w, h, l); *(uint32_t*)&Buh[oB + 6] = h; *(uint32_t*)&Bul[oB + 6] = l;
            __syncthreads();
        }
    }

    // ---- epilogue ----
#pragma unroll
    for (int mf = 0; mf < 2; mf++) {
        int rA = base + wm * 32 + mf * 16 + (lane >> 2);
        float wa = g_w[rA], wb = g_w[rA + 8];
#pragma unroll
        for (int nf = 0; nf < 4; nf++) {
            int col = j0 + wn * 32 + nf * 8 + (lane & 3) * 2;
            float o0 = silu_f(accg[mf][nf][0]) * accu[mf][nf][0] * wa;
            float o1 = silu_f(accg[mf][nf][1]) * accu[mf][nf][1] * wa;
            float o2 = silu_f(accg[mf][nf][2]) * accu[mf][nf][2] * wb;
            float o3 = silu_f(accg[mf][nf][3]) * accu[mf][nf][3] * wb;
            uint32_t h, l;
            split2(o0, o1, h, l);
            *(uint32_t*)&g_ih[(size_t)rA * NI + col] = h;
            *(uint32_t*)&g_il[(size_t)rA * NI + col] = l;
            split2(o2, o3, h, l);
            *(uint32_t*)&g_ih[(size_t)(rA + 8) * NI + col] = h;
            *(uint32_t*)&g_il[(size_t)(rA + 8) * NI + col] = l;
        }
    }
}

// ---------------- GEMM2: out[t,:] += inter @ W2[e] ----------------------------
__global__ __launch_bounds__(256, 2)
void k_gemm2(const float* __restrict__ W2, float* __restrict__ out) {
    int tile = blockIdx.y;
    int e = g_tile_e[tile];
    if (e < 0) return;
    int base = g_tile_base[tile];
    int n0 = blockIdx.x * 64;

    __shared__ __align__(16) __nv_bfloat16 Ah[BM * ASTR], Al[BM * ASTR];
    __shared__ __align__(16) __nv_bfloat16 Bh[KC * BSTR], Bl[KC * BSTR];

    int tid = threadIdx.x, lane = tid & 31, wid = tid >> 5;
    int wm = wid & 3, wn = wid >> 2;

    const float* W = W2 + (size_t)e * NI * NH;

    int arow = tid >> 1, akp = (tid & 1) * 16;
    const __nv_bfloat16* ih = g_ih + (size_t)(base + arow) * NI + akp;
    const __nv_bfloat16* il = g_il + (size_t)(base + arow) * NI + akp;
    int bkr = tid >> 3, bc = (tid & 7) * 8;
    const float* wbase = W + (size_t)bkr * NH + n0 + bc;
    int oA = arow * ASTR + akp;
    int oB = bkr * BSTR + bc;

    uint32_t sAh = smem_u32(Ah), sAl = smem_u32(Al);
    uint32_t sBh = smem_u32(Bh), sBl = smem_u32(Bl);

    uint32_t aoff[2], boff[2];
#pragma unroll
    for (int mf = 0; mf < 2; mf++)
        aoff[mf] = (uint32_t)((wm * 32 + mf * 16 + (lane & 15)) * (ASTR * 2) + (lane >> 4) * 16);
#pragma unroll
    for (int nb = 0; nb < 2; nb++)
        boff[nb] = (uint32_t)((lane & 15) * (BSTR * 2) + (wn * 32 + nb * 16 + (lane >> 4) * 8) * 2);

    float acc[2][4][4] = {};
    const int NC = NI / KC;

    // ---- prologue ----
    {
        const uint4* ph = (const uint4*)ih;
        const uint4* pl = (const uint4*)il;
        uint4 vh0 = ph[0], vh1 = ph[1], vl0 = pl[0], vl1 = pl[1];
        float4 b0 = *(const float4*)wbase, b1 = *(const float4*)(wbase + 4);
        *(uint4*)&Ah[oA] = vh0; *(uint4*)&Ah[oA + 8] = vh1;
        *(uint4*)&Al[oA] = vl0; *(uint4*)&Al[oA + 8] = vl1;
        uint32_t h, l;
        split2(b0.x, b0.y, h, l); *(uint32_t*)&Bh[oB + 0] = h; *(uint32_t*)&Bl[oB + 0] = l;
        split2(b0.z, b0.w, h, l); *(uint32_t*)&Bh[oB + 2] = h; *(uint32_t*)&Bl[oB + 2] = l;
        split2(b1.x, b1.y, h, l); *(uint32_t*)&Bh[oB + 4] = h; *(uint32_t*)&Bl[oB + 4] = l;
        split2(b1.z, b1.w, h, l); *(uint32_t*)&Bh[oB + 6] = h; *(uint32_t*)&Bl[oB + 6] = l;
    }
    __syncthreads();

    for (int c = 0; c < NC; c++) {
        bool more = (c + 1 < NC);
        float4 b0, b1;
        if (more) {
            const float* pb = wbase + (size_t)((c + 1) * KC) * NH;
            b0 = *(const float4*)pb; b1 = *(const float4*)(pb + 4);
        }
#pragma unroll
        for (int s = 0; s < 2; s++) {
            uint32_t ah[2][4], al[2][4], bb[2][4];
            uint32_t as_ = (uint32_t)(s * 32), bs_ = (uint32_t)(s * 16 * BSTR * 2);
            ldm_x4(ah[0], sAh + aoff[0] + as_);
            ldm_x4(ah[1], sAh + aoff[1] + as_);
            ldm_x4(al[0], sAl + aoff[0] + as_);
            ldm_x4(al[1], sAl + aoff[1] + as_);
            ldm_x4t(bb[0], sBh + boff[0] + bs_);
            ldm_x4t(bb[1], sBh + boff[1] + bs_);
#pragma unroll
            for (int mf = 0; mf < 2; mf++)
#pragma unroll
                for (int nb = 0; nb < 2; nb++)
#pragma unroll
                    for (int f = 0; f < 2; f++) {
                        mma_bf16(acc[mf][nb * 2 + f], ah[mf], &bb[nb][f * 2]);
                        mma_bf16(acc[mf][nb * 2 + f], al[mf], &bb[nb][f * 2]);
                    }
            ldm_x4t(bb[0], sBl + boff[0] + bs_);
            ldm_x4t(bb[1], sBl + boff[1] + bs_);
#pragma unroll
            for (int mf = 0; mf < 2; mf++)
#pragma unroll
                for (int nb = 0; nb < 2; nb++)
#pragma unroll
                    for (int f = 0; f < 2; f++)
                        mma_bf16(acc[mf][nb * 2 + f], ah[mf], &bb[nb][f * 2]);
        }
        __syncthreads();
        if (more) {
            int k0 = (c + 1) * KC;
            const uint4* ph = (const uint4*)(ih + k0);
            const uint4* pl = (const uint4*)(il + k0);
            uint4 vh0 = ph[0], vh1 = ph[1], vl0 = pl[0], vl1 = pl[1];
            *(uint4*)&Ah[oA] = vh0; *(uint4*)&Ah[oA + 8] = vh1;
            *(uint4*)&Al[oA] = vl0; *(uint4*)&Al[oA + 8] = vl1;
            uint32_t h, l;
            split2(b0.x, b0.y, h, l); *(uint32_t*)&Bh[oB + 0] = h; *(uint32_t*)&Bl[oB + 0] = l;
            split2(b0.z, b0.w, h, l); *(uint32_t*)&Bh[oB + 2] = h; *(uint32_t*)&Bl[oB + 2] = l;
            split2(b1.x, b1.y, h, l); *(uint32_t*)&Bh[oB + 4] = h; *(uint32_t*)&Bl[oB + 4] = l;
            split2(b1.z, b1.w, h, l); *(uint32_t*)&Bh[oB + 6] = h; *(uint32_t*)&Bl[oB + 6] = l;
            __syncthreads();
        }
    }

#pragma unroll
    for (int mf = 0; mf < 2; mf++) {
        int rA = base + wm * 32 + mf * 16 + (lane >> 2);
        int tA = g_tok[rA], tB = g_tok[rA + 8];
#pragma unroll
        for (int nf = 0; nf < 4; nf++) {
            int col = n0 + wn * 32 + nf * 8 + (lane & 3) * 2;
            atomicAdd(&out[(size_t)tA * NH + col],     acc[mf][nf][0]);
            atomicAdd(&out[(size_t)tA * NH + col + 1], acc[mf][nf][1]);
            atomicAdd(&out[(size_t)tB * NH + col],     acc[mf][nf][2]);
            atomicAdd(&out[(size_t)tB * NH + col + 1], acc[mf][nf][3]);
        }
    }
}

// ---------------- launcher ----------------------------------------------------
extern "C" void kernel_launch(void* const* d_in, const int* in_sizes, int n_in,
                              void* d_out, int out_size) {
    const float* x   = (const float*)d_in[0];
    const int*   idx = (const int*)d_in[1];
    const float* w   = (const float*)d_in[2];
    const float* W1  = (const float*)d_in[3];
    const float* W2  = (const float*)d_in[4];
    float* out = (float*)d_out;

    cudaMemsetAsync(out, 0, (size_t)out_size * sizeof(float));

    k_r0<<<(PADS + 255) / 256, 256>>>(idx);
    k_r1<<<TKP / 256, 256>>>(idx);
    k_r2<<<1, 256>>>(idx, w);

    dim3 g1(NI / 64, MAXTT);
    k_gemm1<<<g1, 256>>>(x, W1);

    dim3 g2(NH / 64, MAXTT);
    k_gemm2<<<g2, 256>>>(W2, out);
}

// round 11
// speedup vs baseline: 1.9813x; 1.4282x over previous
#include <cuda_runtime.h>
#include <cuda_fp16.h>
#include <cstdint>

#define NE 32
#define NH 2048
#define NI 768
#define TWO_I 1536
#define NK 4
#define TKP 8192
#define PADS 12288
#define MAXTT 128
#define BM 128
#define KC 32
#define ASTR 40
#define BSTR 72

// ---------------- device scratch ---------------------------------------------
__device__ int   g_cnt[NE];
__device__ int   g_cur[NE];
__device__ int   g_tok[PADS];
__device__ float g_w[PADS];
__device__ int   g_is64;
__device__ int   g_tile_e[MAXTT];
__device__ int   g_tile_base[MAXTT];
__device__ __half g_i[(size_t)PADS * NI];     // fp16 intermediate

// ---------------- helpers -----------------------------------------------------
__device__ __forceinline__ uint32_t smem_u32(const void* p) {
    uint32_t a;
    asm("{ .reg .u64 t; cvta.to.shared.u64 t, %1; cvt.u32.u64 %0, t; }" : "=r"(a) : "l"(p));
    return a;
}
__device__ __forceinline__ void ldm_x4(uint32_t* r, uint32_t addr) {
    asm volatile("ldmatrix.sync.aligned.m8n8.x4.shared.b16 {%0,%1,%2,%3}, [%4];"
        : "=r"(r[0]), "=r"(r[1]), "=r"(r[2]), "=r"(r[3]) : "r"(addr));
}
__device__ __forceinline__ void ldm_x4t(uint32_t* r, uint32_t addr) {
    asm volatile("ldmatrix.sync.aligned.m8n8.x4.trans.shared.b16 {%0,%1,%2,%3}, [%4];"
        : "=r"(r[0]), "=r"(r[1]), "=r"(r[2]), "=r"(r[3]) : "r"(addr));
}
__device__ __forceinline__ void mma_fp16(float* d, const uint32_t* a, const uint32_t* b) {
    asm volatile("mma.sync.aligned.m16n8k16.row.col.f32.f16.f16.f32 "
        "{%0,%1,%2,%3}, {%4,%5,%6,%7}, {%8,%9}, {%0,%1,%2,%3};"
        : "+f"(d[0]), "+f"(d[1]), "+f"(d[2]), "+f"(d[3])
        : "r"(a[0]), "r"(a[1]), "r"(a[2]), "r"(a[3]), "r"(b[0]), "r"(b[1]));
}
__device__ __forceinline__ uint32_t pk2(float f0, float f1) {
    __half2 h = __floats2half2_rn(f0, f1);
    return *reinterpret_cast<uint32_t*>(&h);
}
__device__ __forceinline__ float silu_f(float v) { return v / (1.0f + __expf(-v)); }

__device__ __forceinline__ int fetch_idx(const int* __restrict__ idx, int i, int is64) {
    return is64 ? idx[2 * i] : idx[i];
}
__device__ __forceinline__ int keep_pair(const int* __restrict__ idx, int t, int k,
                                         int e, int is64) {
    for (int k2 = k + 1; k2 < NK; k2++)
        if (fetch_idx(idx, t * NK + k2, is64) == e) return 0;
    return 1;
}

// ---------------- routing: 3 kernels (gemm1 = 4th launch for ncu) -------------
__global__ void k_r0(const int* __restrict__ idx) {
    int i = blockIdx.x * blockDim.x + threadIdx.x;
    if (i < PADS) { g_tok[i] = 0; g_w[i] = 0.f; }
    if (i < NE) g_cnt[i] = 0;
    if (i == 0) {
        int ok = 1;
        for (int j = 0; j < 64; j++) if (idx[2 * j + 1] != 0) { ok = 0; break; }
        g_is64 = ok;
    }
}
__global__ void k_r1(const int* __restrict__ idx) {
    int i = blockIdx.x * blockDim.x + threadIdx.x;
    if (i < TKP) {
        int is64 = g_is64;
        int t = i / NK, k = i % NK;
        int e = fetch_idx(idx, i, is64);
        if (keep_pair(idx, t, k, e, is64)) atomicAdd(&g_cnt[e], 1);
    }
}
__global__ void k_r2(const int* __restrict__ idx, const float* __restrict__ wgt) {
    int tid = threadIdx.x;
    if (tid == 0) {
        int pb = 0, tl = 0;
        for (int e = 0; e < NE; e++) {
            g_cur[e] = pb;
            int nt = (g_cnt[e] + BM - 1) / BM;
            for (int j = 0; j < nt; j++) { g_tile_e[tl] = e; g_tile_base[tl] = pb + j * BM; tl++; }
            pb += nt * BM;
        }
        for (int t2 = tl; t2 < MAXTT; t2++) g_tile_e[t2] = -1;
    }
    __syncthreads();
    int is64 = g_is64;
    for (int i = tid; i < TKP; i += blockDim.x) {
        int t = i / NK, k = i % NK;
        int e = fetch_idx(idx, i, is64);
        if (keep_pair(idx, t, k, e, is64)) {
            int pos = atomicAdd(&g_cur[e], 1);
            g_tok[pos] = t; g_w[pos] = wgt[i];
        }
    }
}

// ---------------- GEMM1: inter = silu(x@Wg)*(x@Wu)*w (fp16) -------------------
__global__ __launch_bounds__(256, 2)
void k_gemm1(const float* __restrict__ x, const float* __restrict__ W1) {
    int tile = blockIdx.y;
    int e = g_tile_e[tile];
    if (e < 0) return;
    int base = g_tile_base[tile];
    int j0 = blockIdx.x * 64;

    __shared__ __align__(16) __half Ash[BM * ASTR];
    __shared__ __align__(16) __half Bg[KC * BSTR];
    __shared__ __align__(16) __half Bu[KC * BSTR];

    int tid = threadIdx.x, lane = tid & 31, wid = tid >> 5;
    int wm = wid & 3, wn = wid >> 2;

    const float* W = W1 + (size_t)e * NH * TWO_I;

    int arow = tid >> 1, akp = (tid & 1) * 16;
    const float* xrow = x + (size_t)g_tok[base + arow] * NH + akp;
    int bkr = tid >> 3, bc = (tid & 7) * 8;
    const float* wbase = W + (size_t)bkr * TWO_I + j0 + bc;
    int oA = arow * ASTR + akp;
    int oB = bkr * BSTR + bc;

    uint32_t sA = smem_u32(Ash);
    uint32_t sBg = smem_u32(Bg), sBu = smem_u32(Bu);

    uint32_t aoff[2], boff[2];
#pragma unroll
    for (int mf = 0; mf < 2; mf++)
        aoff[mf] = (uint32_t)((wm * 32 + mf * 16 + (lane & 15)) * (ASTR * 2) + (lane >> 4) * 16);
#pragma unroll
    for (int nb = 0; nb < 2; nb++)
        boff[nb] = (uint32_t)((lane & 15) * (BSTR * 2) + (wn * 32 + nb * 16 + (lane >> 4) * 8) * 2);

    float accg[2][4][4] = {}, accu[2][4][4] = {};
    const int NC = NH / KC;

    // ---- prologue: chunk 0 ----
    {
        const float4* px = (const float4*)xrow;
        float4 a0 = px[0], a1 = px[1], a2 = px[2], a3 = px[3];
        float4 gg0 = *(const float4*)wbase,        gg1 = *(const float4*)(wbase + 4);
        float4 uu0 = *(const float4*)(wbase + NI), uu1 = *(const float4*)(wbase + NI + 4);
        *(uint32_t*)&Ash[oA + 0]  = pk2(a0.x, a0.y);
        *(uint32_t*)&Ash[oA + 2]  = pk2(a0.z, a0.w);
        *(uint32_t*)&Ash[oA + 4]  = pk2(a1.x, a1.y);
        *(uint32_t*)&Ash[oA + 6]  = pk2(a1.z, a1.w);
        *(uint32_t*)&Ash[oA + 8]  = pk2(a2.x, a2.y);
        *(uint32_t*)&Ash[oA + 10] = pk2(a2.z, a2.w);
        *(uint32_t*)&Ash[oA + 12] = pk2(a3.x, a3.y);
        *(uint32_t*)&Ash[oA + 14] = pk2(a3.z, a3.w);
        *(uint32_t*)&Bg[oB + 0] = pk2(gg0.x, gg0.y);
        *(uint32_t*)&Bg[oB + 2] = pk2(gg0.z, gg0.w);
        *(uint32_t*)&Bg[oB + 4] = pk2(gg1.x, gg1.y);
        *(uint32_t*)&Bg[oB + 6] = pk2(gg1.z, gg1.w);
        *(uint32_t*)&Bu[oB + 0] = pk2(uu0.x, uu0.y);
        *(uint32_t*)&Bu[oB + 2] = pk2(uu0.z, uu0.w);
        *(uint32_t*)&Bu[oB + 4] = pk2(uu1.x, uu1.y);
        *(uint32_t*)&Bu[oB + 6] = pk2(uu1.z, uu1.w);
    }
    __syncthreads();

    for (int c = 0; c < NC; c++) {
        bool more = (c + 1 < NC);
        // ---- prefetch next B (DRAM weights) into registers over the MMA ----
        float4 gg0, gg1, uu0, uu1;
        if (more) {
            const float* pg = wbase + (size_t)((c + 1) * KC) * TWO_I;
            gg0 = *(const float4*)pg;        gg1 = *(const float4*)(pg + 4);
            uu0 = *(const float4*)(pg + NI); uu1 = *(const float4*)(pg + NI + 4);
        }
        // ---- MMA on chunk c ----
#pragma unroll
        for (int s = 0; s < 2; s++) {
            uint32_t ah[2][4], bg[2][4], bu[2][4];
            uint32_t as_ = (uint32_t)(s * 32), bs_ = (uint32_t)(s * 16 * BSTR * 2);
            ldm_x4(ah[0], sA + aoff[0] + as_);
            ldm_x4(ah[1], sA + aoff[1] + as_);
            ldm_x4t(bg[0], sBg + boff[0] + bs_);
            ldm_x4t(bg[1], sBg + boff[1] + bs_);
            ldm_x4t(bu[0], sBu + boff[0] + bs_);
            ldm_x4t(bu[1], sBu + boff[1] + bs_);
#pragma unroll
            for (int mf = 0; mf < 2; mf++)
#pragma unroll
                for (int nb = 0; nb < 2; nb++)
#pragma unroll
                    for (int f = 0; f < 2; f++) {
                        mma_fp16(accg[mf][nb * 2 + f], ah[mf], &bg[nb][f * 2]);
                        mma_fp16(accu[mf][nb * 2 + f], ah[mf], &bu[nb][f * 2]);
                    }
        }
        __syncthreads();
        // ---- store chunk c+1: A direct (L2-resident x), B from prefetch regs --
        if (more) {
            const float4* px = (const float4*)(xrow + (c + 1) * KC);
            float4 a0 = px[0], a1 = px[1], a2 = px[2], a3 = px[3];
            *(uint32_t*)&Ash[oA + 0]  = pk2(a0.x, a0.y);
            *(uint32_t*)&Ash[oA + 2]  = pk2(a0.z, a0.w);
            *(uint32_t*)&Ash[oA + 4]  = pk2(a1.x, a1.y);
            *(uint32_t*)&Ash[oA + 6]  = pk2(a1.z, a1.w);
            *(uint32_t*)&Ash[oA + 8]  = pk2(a2.x, a2.y);
            *(uint32_t*)&Ash[oA + 10] = pk2(a2.z, a2.w);
            *(uint32_t*)&Ash[oA + 12] = pk2(a3.x, a3.y);
            *(uint32_t*)&Ash[oA + 14] = pk2(a3.z, a3.w);
            *(uint32_t*)&Bg[oB + 0] = pk2(gg0.x, gg0.y);
            *(uint32_t*)&Bg[oB + 2] = pk2(gg0.z, gg0.w);
            *(uint32_t*)&Bg[oB + 4] = pk2(gg1.x, gg1.y);
            *(uint32_t*)&Bg[oB + 6] = pk2(gg1.z, gg1.w);
            *(uint32_t*)&Bu[oB + 0] = pk2(uu0.x, uu0.y);
            *(uint32_t*)&Bu[oB + 2] = pk2(uu0.z, uu0.w);
            *(uint32_t*)&Bu[oB + 4] = pk2(uu1.x, uu1.y);
            *(uint32_t*)&Bu[oB + 6] = pk2(uu1.z, uu1.w);
            __syncthreads();
        }
    }

    // ---- epilogue: silu(gate)*up*w -> fp16 intermediate ----
#pragma unroll
    for (int mf = 0; mf < 2; mf++) {
        int rA = base + wm * 32 + mf * 16 + (lane >> 2);
        float wa = g_w[rA], wb = g_w[rA + 8];
#pragma unroll
        for (int nf = 0; nf < 4; nf++) {
            int col = j0 + wn * 32 + nf * 8 + (lane & 3) * 2;
            float o0 = silu_f(accg[mf][nf][0]) * accu[mf][nf][0] * wa;
            float o1 = silu_f(accg[mf][nf][1]) * accu[mf][nf][1] * wa;
            float o2 = silu_f(accg[mf][nf][2]) * accu[mf][nf][2] * wb;
            float o3 = silu_f(accg[mf][nf][3]) * accu[mf][nf][3] * wb;
            *(uint32_t*)&g_i[(size_t)rA * NI + col]       = pk2(o0, o1);
            *(uint32_t*)&g_i[(size_t)(rA + 8) * NI + col] = pk2(o2, o3);
        }
    }
}

// ---------------- GEMM2: out[t,:] += inter @ W2[e] ----------------------------
__global__ __launch_bounds__(256, 2)
void k_gemm2(const float* __restrict__ W2, float* __restrict__ out) {
    int tile = blockIdx.y;
    int e = g_tile_e[tile];
    if (e < 0) return;
    int base = g_tile_base[tile];
    int n0 = blockIdx.x * 64;

    __shared__ __align__(16) __half Ash[BM * ASTR];
    __shared__ __align__(16) __half Bs[KC * BSTR];

    int tid = threadIdx.x, lane = tid & 31, wid = tid >> 5;
    int wm = wid & 3, wn = wid >> 2;

    const float* W = W2 + (size_t)e * NI * NH;

    int arow = tid >> 1, akp = (tid & 1) * 16;
    const __half* ip = g_i + (size_t)(base + arow) * NI + akp;
    int bkr = tid >> 3, bc = (tid & 7) * 8;
    const float* wbase = W + (size_t)bkr * NH + n0 + bc;
    int oA = arow * ASTR + akp;
    int oB = bkr * BSTR + bc;

    uint32_t sA = smem_u32(Ash), sB = smem_u32(Bs);

    uint32_t aoff[2], boff[2];
#pragma unroll
    for (int mf = 0; mf < 2; mf++)
        aoff[mf] = (uint32_t)((wm * 32 + mf * 16 + (lane & 15)) * (ASTR * 2) + (lane >> 4) * 16);
#pragma unroll
    for (int nb = 0; nb < 2; nb++)
        boff[nb] = (uint32_t)((lane & 15) * (BSTR * 2) + (wn * 32 + nb * 16 + (lane >> 4) * 8) * 2);

    float acc[2][4][4] = {};
    const int NC = NI / KC;

    // ---- prologue ----
    {
        const uint4* pa = (const uint4*)ip;
        uint4 v0 = pa[0], v1 = pa[1];
        float4 b0 = *(const float4*)wbase, b1 = *(const float4*)(wbase + 4);
        *(uint4*)&Ash[oA]     = v0;
        *(uint4*)&Ash[oA + 8] = v1;
        *(uint32_t*)&Bs[oB + 0] = pk2(b0.x, b0.y);
        *(uint32_t*)&Bs[oB + 2] = pk2(b0.z, b0.w);
        *(uint32_t*)&Bs[oB + 4] = pk2(b1.x, b1.y);
        *(uint32_t*)&Bs[oB + 6] = pk2(b1.z, b1.w);
    }
    __syncthreads();

    for (int c = 0; c < NC; c++) {
        bool more = (c + 1 < NC);
        float4 b0, b1;
        uint4 v0, v1;
        if (more) {
            int k0 = (c + 1) * KC;
            const uint4* pa = (const uint4*)(ip + k0);
            v0 = pa[0]; v1 = pa[1];
            const float* pb = wbase + (size_t)k0 * NH;
            b0 = *(const float4*)pb; b1 = *(const float4*)(pb + 4);
        }
#pragma unroll
        for (int s = 0; s < 2; s++) {
            uint32_t ah[2][4], bb[2][4];
            uint32_t as_ = (uint32_t)(s * 32), bs_ = (uint32_t)(s * 16 * BSTR * 2);
            ldm_x4(ah[0], sA + aoff[0] + as_);
            ldm_x4(ah[1], sA + aoff[1] + as_);
            ldm_x4t(bb[0], sB + boff[0] + bs_);
            ldm_x4t(bb[1], sB + boff[1] + bs_);
#pragma unroll
            for (int mf = 0; mf < 2; mf++)
#pragma unroll
                for (int nb = 0; nb < 2; nb++)
#pragma unroll
                    for (int f = 0; f < 2; f++)
                        mma_fp16(acc[mf][nb * 2 + f], ah[mf], &bb[nb][f * 2]);
        }
        __syncthreads();
        if (more) {
            *(uint4*)&Ash[oA]     = v0;
            *(uint4*)&Ash[oA + 8] = v1;
            *(uint32_t*)&Bs[oB + 0] = pk2(b0.x, b0.y);
            *(uint32_t*)&Bs[oB + 2] = pk2(b0.z, b0.w);
            *(uint32_t*)&Bs[oB + 4] = pk2(b1.x, b1.y);
            *(uint32_t*)&Bs[oB + 6] = pk2(b1.z, b1.w);
            __syncthreads();
        }
    }

#pragma unroll
    for (int mf = 0; mf < 2; mf++) {
        int rA = base + wm * 32 + mf * 16 + (lane >> 2);
        int tA = g_tok[rA], tB = g_tok[rA + 8];
#pragma unroll
        for (int nf = 0; nf < 4; nf++) {
            int col = n0 + wn * 32 + nf * 8 + (lane & 3) * 2;
            atomicAdd(&out[(size_t)tA * NH + col],     acc[mf][nf][0]);
            atomicAdd(&out[(size_t)tA * NH + col + 1], acc[mf][nf][1]);
            atomicAdd(&out[(size_t)tB * NH + col],     acc[mf][nf][2]);
            atomicAdd(&out[(size_t)tB * NH + col + 1], acc[mf][nf][3]);
        }
    }
}

// ---------------- launcher ----------------------------------------------------
extern "C" void kernel_launch(void* const* d_in, const int* in_sizes, int n_in,
                              void* d_out, int out_size) {
    const float* x   = (const float*)d_in[0];
    const int*   idx = (const int*)d_in[1];
    const float* w   = (const float*)d_in[2];
    const float* W1  = (const float*)d_in[3];
    const float* W2  = (const float*)d_in[4];
    float* out = (float*)d_out;

    cudaMemsetAsync(out, 0, (size_t)out_size * sizeof(float));

    k_r0<<<(PADS + 255) / 256, 256>>>(idx);
    k_r1<<<TKP / 256, 256>>>(idx);
    k_r2<<<1, 256>>>(idx, w);

    dim3 g1(NI / 64, MAXTT);
    k_gemm1<<<g1, 256>>>(x, W1);

    dim3 g2(NH / 64, MAXTT);
    k_gemm2<<<g2, 256>>>(W2, out);
}

// round 12
// speedup vs baseline: 2.1252x; 1.0726x over previous
#include <cuda_runtime.h>
#include <cuda_fp16.h>
#include <cstdint>

#define NE 32
#define NH 2048
#define NI 768
#define TWO_I 1536
#define NK 4
#define NT 2048
#define TKP 8192
#define PADS 12288
#define MAXTT 128
#define BM 128
#define KC 32
#define ASTR 40
#define BSTR 72

// ---------------- device scratch ---------------------------------------------
__device__ int   g_cnt[NE];
__device__ int   g_cur[NE];
__device__ int   g_tok[PADS];
__device__ float g_w[PADS];
__device__ int   g_is64;
__device__ int   g_tile_e[MAXTT];
__device__ int   g_tile_base[MAXTT];
__device__ __half g_xh[(size_t)NT * NH];      // fp16 pre-converted hidden states
__device__ __half g_i[(size_t)PADS * NI];     // fp16 intermediate

// ---------------- helpers -----------------------------------------------------
__device__ __forceinline__ uint32_t smem_u32(const void* p) {
    uint32_t a;
    asm("{ .reg .u64 t; cvta.to.shared.u64 t, %1; cvt.u32.u64 %0, t; }" : "=r"(a) : "l"(p));
    return a;
}
__device__ __forceinline__ void ldm_x4(uint32_t* r, uint32_t addr) {
    asm volatile("ldmatrix.sync.aligned.m8n8.x4.shared.b16 {%0,%1,%2,%3}, [%4];"
        : "=r"(r[0]), "=r"(r[1]), "=r"(r[2]), "=r"(r[3]) : "r"(addr));
}
__device__ __forceinline__ void ldm_x4t(uint32_t* r, uint32_t addr) {
    asm volatile("ldmatrix.sync.aligned.m8n8.x4.trans.shared.b16 {%0,%1,%2,%3}, [%4];"
        : "=r"(r[0]), "=r"(r[1]), "=r"(r[2]), "=r"(r[3]) : "r"(addr));
}
__device__ __forceinline__ void mma_fp16(float* d, const uint32_t* a, const uint32_t* b) {
    asm volatile("mma.sync.aligned.m16n8k16.row.col.f32.f16.f16.f32 "
        "{%0,%1,%2,%3}, {%4,%5,%6,%7}, {%8,%9}, {%0,%1,%2,%3};"
        : "+f"(d[0]), "+f"(d[1]), "+f"(d[2]), "+f"(d[3])
        : "r"(a[0]), "r"(a[1]), "r"(a[2]), "r"(a[3]), "r"(b[0]), "r"(b[1]));
}
__device__ __forceinline__ uint32_t pk2(float f0, float f1) {
    __half2 h = __floats2half2_rn(f0, f1);
    return *reinterpret_cast<uint32_t*>(&h);
}
__device__ __forceinline__ float silu_f(float v) { return v / (1.0f + __expf(-v)); }

__device__ __forceinline__ int fetch_idx(const int* __restrict__ idx, int i, int is64) {
    return is64 ? idx[2 * i] : idx[i];
}
__device__ __forceinline__ int keep_pair(const int* __restrict__ idx, int t, int k,
                                         int e, int is64) {
    for (int k2 = k + 1; k2 < NK; k2++)
        if (fetch_idx(idx, t * NK + k2, is64) == e) return 0;
    return 1;
}

// ---------------- x fp32->fp16 + routing init (one kernel) --------------------
__global__ void k_xc(const float* __restrict__ x, const int* __restrict__ idx) {
    int i = blockIdx.x * blockDim.x + threadIdx.x;     // one thread = 8 elements
    const float4* p = (const float4*)(x + (size_t)i * 8);
    float4 v0 = p[0], v1 = p[1];
    uint4 o;
    o.x = pk2(v0.x, v0.y); o.y = pk2(v0.z, v0.w);
    o.z = pk2(v1.x, v1.y); o.w = pk2(v1.z, v1.w);
    *(uint4*)(g_xh + (size_t)i * 8) = o;
    if (i < PADS) { g_tok[i] = 0; g_w[i] = 0.f; }
    if (i < NE) g_cnt[i] = 0;
    if (i == 0) {
        int ok = 1;
        for (int j = 0; j < 64; j++) if (idx[2 * j + 1] != 0) { ok = 0; break; }
        g_is64 = ok;
    }
}
__global__ void k_r1(const int* __restrict__ idx) {
    int i = blockIdx.x * blockDim.x + threadIdx.x;
    if (i < TKP) {
        int is64 = g_is64;
        int t = i / NK, k = i % NK;
        int e = fetch_idx(idx, i, is64);
        if (keep_pair(idx, t, k, e, is64)) atomicAdd(&g_cnt[e], 1);
    }
}
__global__ void k_r2(const int* __restrict__ idx, const float* __restrict__ wgt) {
    int tid = threadIdx.x;
    if (tid == 0) {
        int pb = 0, tl = 0;
        for (int e = 0; e < NE; e++) {
            g_cur[e] = pb;
            int nt = (g_cnt[e] + BM - 1) / BM;
            for (int j = 0; j < nt; j++) { g_tile_e[tl] = e; g_tile_base[tl] = pb + j * BM; tl++; }
            pb += nt * BM;
        }
        for (int t2 = tl; t2 < MAXTT; t2++) g_tile_e[t2] = -1;
    }
    __syncthreads();
    int is64 = g_is64;
    for (int i = tid; i < TKP; i += blockDim.x) {
        int t = i / NK, k = i % NK;
        int e = fetch_idx(idx, i, is64);
        if (keep_pair(idx, t, k, e, is64)) {
            int pos = atomicAdd(&g_cur[e], 1);
            g_tok[pos] = t; g_w[pos] = wgt[i];
        }
    }
}

// ---------------- GEMM1: inter = silu(x@Wg)*(x@Wu)*w (fp16) -------------------
__global__ __launch_bounds__(256, 2)
void k_gemm1(const float* __restrict__ W1) {
    int tile = blockIdx.y;
    int e = g_tile_e[tile];
    if (e < 0) return;
    int base = g_tile_base[tile];
    int j0 = blockIdx.x * 64;

    __shared__ __align__(16) __half Ab[2][BM * ASTR];
    __shared__ __align__(16) __half Bgb[2][KC * BSTR];
    __shared__ __align__(16) __half Bub[2][KC * BSTR];

    int tid = threadIdx.x, lane = tid & 31, wid = tid >> 5;
    int wm = wid & 3, wn = wid >> 2;

    const float* W = W1 + (size_t)e * NH * TWO_I;

    int arow = tid >> 1, akp = (tid & 1) * 16;
    const __half* xrowh = g_xh + (size_t)g_tok[base + arow] * NH + akp;
    int bkr = tid >> 3, bc = (tid & 7) * 8;
    const float* wbase = W + (size_t)bkr * TWO_I + j0 + bc;
    int oA = arow * ASTR + akp;
    int oB = bkr * BSTR + bc;

    uint32_t sA[2] = { smem_u32(Ab[0]), smem_u32(Ab[1]) };
    uint32_t sBg[2] = { smem_u32(Bgb[0]), smem_u32(Bgb[1]) };
    uint32_t sBu[2] = { smem_u32(Bub[0]), smem_u32(Bub[1]) };

    uint32_t aoff[2], boff[2];
#pragma unroll
    for (int mf = 0; mf < 2; mf++)
        aoff[mf] = (uint32_t)((wm * 32 + mf * 16 + (lane & 15)) * (ASTR * 2) + (lane >> 4) * 16);
#pragma unroll
    for (int nb = 0; nb < 2; nb++)
        boff[nb] = (uint32_t)((lane & 15) * (BSTR * 2) + (wn * 32 + nb * 16 + (lane >> 4) * 8) * 2);

    float accg[2][4][4] = {}, accu[2][4][4] = {};
    const int NC = NH / KC;

    // ---- prologue: load+convert chunk 0 into buf 0 ----
    {
        const uint4* pa = (const uint4*)xrowh;
        uint4 va0 = pa[0], va1 = pa[1];
        float4 gg0 = *(const float4*)wbase,        gg1 = *(const float4*)(wbase + 4);
        float4 uu0 = *(const float4*)(wbase + NI), uu1 = *(const float4*)(wbase + NI + 4);
        *(uint4*)&Ab[0][oA]     = va0;
        *(uint4*)&Ab[0][oA + 8] = va1;
        *(uint32_t*)&Bgb[0][oB + 0] = pk2(gg0.x, gg0.y);
        *(uint32_t*)&Bgb[0][oB + 2] = pk2(gg0.z, gg0.w);
        *(uint32_t*)&Bgb[0][oB + 4] = pk2(gg1.x, gg1.y);
        *(uint32_t*)&Bgb[0][oB + 6] = pk2(gg1.z, gg1.w);
        *(uint32_t*)&Bub[0][oB + 0] = pk2(uu0.x, uu0.y);
        *(uint32_t*)&Bub[0][oB + 2] = pk2(uu0.z, uu0.w);
        *(uint32_t*)&Bub[0][oB + 4] = pk2(uu1.x, uu1.y);
        *(uint32_t*)&Bub[0][oB + 6] = pk2(uu1.z, uu1.w);
    }
    __syncthreads();

    for (int c = 0; c < NC; c++) {
        int st = c & 1, ns = st ^ 1;
        bool more = (c + 1 < NC);
        // ---- 1) issue LDGs for chunk c+1 (fly over the MMA below) ----
        uint4 va0, va1; float4 gg0, gg1, uu0, uu1;
        if (more) {
            int k0 = (c + 1) * KC;
            const uint4* pa = (const uint4*)(xrowh + k0);
            va0 = pa[0]; va1 = pa[1];
            const float* pg = wbase + (size_t)k0 * TWO_I;
            gg0 = *(const float4*)pg;        gg1 = *(const float4*)(pg + 4);
            uu0 = *(const float4*)(pg + NI); uu1 = *(const float4*)(pg + NI + 4);
        }
        // ---- 2) MMA on chunk c from buf[st] ----
#pragma unroll
        for (int s = 0; s < 2; s++) {
            uint32_t ah[2][4], bg[2][4], bu[2][4];
            uint32_t as_ = (uint32_t)(s * 32), bs_ = (uint32_t)(s * 16 * BSTR * 2);
            ldm_x4(ah[0], sA[st] + aoff[0] + as_);
            ldm_x4(ah[1], sA[st] + aoff[1] + as_);
            ldm_x4t(bg[0], sBg[st] + boff[0] + bs_);
            ldm_x4t(bg[1], sBg[st] + boff[1] + bs_);
            ldm_x4t(bu[0], sBu[st] + boff[0] + bs_);
            ldm_x4t(bu[1], sBu[st] + boff[1] + bs_);
#pragma unroll
            for (int mf = 0; mf < 2; mf++)
#pragma unroll
                for (int nb = 0; nb < 2; nb++)
#pragma unroll
                    for (int f = 0; f < 2; f++) {
                        mma_fp16(accg[mf][nb * 2 + f], ah[mf], &bg[nb][f * 2]);
                        mma_fp16(accu[mf][nb * 2 + f], ah[mf], &bu[nb][f * 2]);
                    }
        }
        // ---- 3) convert + store chunk c+1 into buf[ns] ----
        if (more) {
            *(uint4*)&Ab[ns][oA]     = va0;
            *(uint4*)&Ab[ns][oA + 8] = va1;
            *(uint32_t*)&Bgb[ns][oB + 0] = pk2(gg0.x, gg0.y);
            *(uint32_t*)&Bgb[ns][oB + 2] = pk2(gg0.z, gg0.w);
            *(uint32_t*)&Bgb[ns][oB + 4] = pk2(gg1.x, gg1.y);
            *(uint32_t*)&Bgb[ns][oB + 6] = pk2(gg1.z, gg1.w);
            *(uint32_t*)&Bub[ns][oB + 0] = pk2(uu0.x, uu0.y);
            *(uint32_t*)&Bub[ns][oB + 2] = pk2(uu0.z, uu0.w);
            *(uint32_t*)&Bub[ns][oB + 4] = pk2(uu1.x, uu1.y);
            *(uint32_t*)&Bub[ns][oB + 6] = pk2(uu1.z, uu1.w);
        }
        __syncthreads();
    }

    // ---- epilogue ----
#pragma unroll
    for (int mf = 0; mf < 2; mf++) {
        int rA = base + wm * 32 + mf * 16 + (lane >> 2);
        float wa = g_w[rA], wb = g_w[rA + 8];
#pragma unroll
        for (int nf = 0; nf < 4; nf++) {
            int col = j0 + wn * 32 + nf * 8 + (lane & 3) * 2;
            float o0 = silu_f(accg[mf][nf][0]) * accu[mf][nf][0] * wa;
            float o1 = silu_f(accg[mf][nf][1]) * accu[mf][nf][1] * wa;
            float o2 = silu_f(accg[mf][nf][2]) * accu[mf][nf][2] * wb;
            float o3 = silu_f(accg[mf][nf][3]) * accu[mf][nf][3] * wb;
            *(uint32_t*)&g_i[(size_t)rA * NI + col]       = pk2(o0, o1);
            *(uint32_t*)&g_i[(size_t)(rA + 8) * NI + col] = pk2(o2, o3);
        }
    }
}

// ---------------- GEMM2: out[t,:] += inter @ W2[e] ----------------------------
__global__ __launch_bounds__(256, 2)
void k_gemm2(const float* __restrict__ W2, float* __restrict__ out) {
    int tile = blockIdx.y;
    int e = g_tile_e[tile];
    if (e < 0) return;
    int base = g_tile_base[tile];
    int n0 = blockIdx.x * 64;

    __shared__ __align__(16) __half Ab[2][BM * ASTR];
    __shared__ __align__(16) __half Bb[2][KC * BSTR];

    int tid = threadIdx.x, lane = tid & 31, wid = tid >> 5;
    int wm = wid & 3, wn = wid >> 2;

    const float* W = W2 + (size_t)e * NI * NH;

    int arow = tid >> 1, akp = (tid & 1) * 16;
    const __half* ip = g_i + (size_t)(base + arow) * NI + akp;
    int bkr = tid >> 3, bc = (tid & 7) * 8;
    const float* wbase = W + (size_t)bkr * NH + n0 + bc;
    int oA = arow * ASTR + akp;
    int oB = bkr * BSTR + bc;

    uint32_t sA[2] = { smem_u32(Ab[0]), smem_u32(Ab[1]) };
    uint32_t sB[2] = { smem_u32(Bb[0]), smem_u32(Bb[1]) };

    uint32_t aoff[2], boff[2];
#pragma unroll
    for (int mf = 0; mf < 2; mf++)
        aoff[mf] = (uint32_t)((wm * 32 + mf * 16 + (lane & 15)) * (ASTR * 2) + (lane >> 4) * 16);
#pragma unroll
    for (int nb = 0; nb < 2; nb++)
        boff[nb] = (uint32_t)((lane & 15) * (BSTR * 2) + (wn * 32 + nb * 16 + (lane >> 4) * 8) * 2);

    float acc[2][4][4] = {};
    const int NC = NI / KC;

    // ---- prologue ----
    {
        const uint4* pa = (const uint4*)ip;
        uint4 v0 = pa[0], v1 = pa[1];
        float4 b0 = *(const float4*)wbase, b1 = *(const float4*)(wbase + 4);
        *(uint4*)&Ab[0][oA]     = v0;
        *(uint4*)&Ab[0][oA + 8] = v1;
        *(uint32_t*)&Bb[0][oB + 0] = pk2(b0.x, b0.y);
        *(uint32_t*)&Bb[0][oB + 2] = pk2(b0.z, b0.w);
        *(uint32_t*)&Bb[0][oB + 4] = pk2(b1.x, b1.y);
        *(uint32_t*)&Bb[0][oB + 6] = pk2(b1.z, b1.w);
    }
    __syncthreads();

    for (int c = 0; c < NC; c++) {
        int st = c & 1, ns = st ^ 1;
        bool more = (c + 1 < NC);
        uint4 v0, v1; float4 b0, b1;
        if (more) {
            int k0 = (c + 1) * KC;
            const uint4* pa = (const uint4*)(ip + k0);
            v0 = pa[0]; v1 = pa[1];
            const float* pb = wbase + (size_t)k0 * NH;
            b0 = *(const float4*)pb; b1 = *(const float4*)(pb + 4);
        }
#pragma unroll
        for (int s = 0; s < 2; s++) {
            uint32_t ah[2][4], bb[2][4];
            uint32_t as_ = (uint32_t)(s * 32), bs_ = (uint32_t)(s * 16 * BSTR * 2);
            ldm_x4(ah[0], sA[st] + aoff[0] + as_);
            ldm_x4(ah[1], sA[st] + aoff[1] + as_);
            ldm_x4t(bb[0], sB[st] + boff[0] + bs_);
            ldm_x4t(bb[1], sB[st] + boff[1] + bs_);
#pragma unroll
            for (int mf = 0; mf < 2; mf++)
#pragma unroll
                for (int nb = 0; nb < 2; nb++)
#pragma unroll
                    for (int f = 0; f < 2; f++)
                        mma_fp16(acc[mf][nb * 2 + f], ah[mf], &bb[nb][f * 2]);
        }
        if (more) {
            *(uint4*)&Ab[ns][oA]     = v0;
            *(uint4*)&Ab[ns][oA + 8] = v1;
            *(uint32_t*)&Bb[ns][oB + 0] = pk2(b0.x, b0.y);
            *(uint32_t*)&Bb[ns][oB + 2] = pk2(b0.z, b0.w);
            *(uint32_t*)&Bb[ns][oB + 4] = pk2(b1.x, b1.y);
            *(uint32_t*)&Bb[ns][oB + 6] = pk2(b1.z, b1.w);
        }
        __syncthreads();
    }

#pragma unroll
    for (int mf = 0; mf < 2; mf++) {
        int rA = base + wm * 32 + mf * 16 + (lane >> 2);
        int tA = g_tok[rA], tB = g_tok[rA + 8];
#pragma unroll
        for (int nf = 0; nf < 4; nf++) {
            int col = n0 + wn * 32 + nf * 8 + (lane & 3) * 2;
            atomicAdd(&out[(size_t)tA * NH + col],     acc[mf][nf][0]);
            atomicAdd(&out[(size_t)tA * NH + col + 1], acc[mf][nf][1]);
            atomicAdd(&out[(size_t)tB * NH + col],     acc[mf][nf][2]);
            atomicAdd(&out[(size_t)tB * NH + col + 1], acc[mf][nf][3]);
        }
    }
}

// ---------------- launcher ----------------------------------------------------
extern "C" void kernel_launch(void* const* d_in, const int* in_sizes, int n_in,
                              void* d_out, int out_size) {
    const float* x   = (const float*)d_in[0];
    const int*   idx = (const int*)d_in[1];
    const float* w   = (const float*)d_in[2];
    const float* W1  = (const float*)d_in[3];
    const float* W2  = (const float*)d_in[4];
    float* out = (float*)d_out;

    cudaMemsetAsync(out, 0, (size_t)out_size * sizeof(float));

    k_xc<<<(NT * NH / 8) / 256, 256>>>(x, idx);   // x->fp16 + routing init
    k_r1<<<TKP / 256, 256>>>(idx);
    k_r2<<<1, 256>>>(idx, w);

    dim3 g1(NI / 64, MAXTT);
    k_gemm1<<<g1, 256>>>(W1);

    dim3 g2(NH / 64, MAXTT);
    k_gemm2<<<g2, 256>>>(W2, out);
}